// round 11
// baseline (speedup 1.0000x reference)
#include <cuda_runtime.h>

#define B_   256
#define IN_  256
#define OUT_ 512
#define EPS_ 1e-7f

__device__ float g_relx[IN_ * OUT_];   // rel_x[i][o]

__device__ __forceinline__ unsigned smem_u32(const void* p) {
    unsigned a;
    asm("{ .reg .u64 t; cvta.to.shared.u64 t, %1; cvt.u32.u64 %0, t; }"
        : "=r"(a) : "l"(p));
    return a;
}

#define CLUSTER_SYNC() do { \
    asm volatile("barrier.cluster.arrive.aligned;" ::: "memory"); \
    asm volatile("barrier.cluster.wait.aligned;"   ::: "memory"); \
} while (0)

// ---------------------------------------------------------------------------
// Kernel 1: rel_x[i,o] = (sum_b min(t[b,o]/(x[b,i]+eps),1)) / colsum[i]
// Tile 32i x 16o, 256 thr (o fastest), 2i x 1o per thread. Grid (8,32)=256.
// (unchanged from R10 — measured stable)
// ---------------------------------------------------------------------------
__global__ void k_relx(const float* __restrict__ x, const float* __restrict__ t) {
    __shared__ float Rs[128][32];
    __shared__ float Ts[128][16];
    __shared__ float ps[8][32];
    __shared__ float s_cs[32];

    const int i0  = blockIdx.x * 32;
    const int o0  = blockIdx.y * 16;
    const int lid = threadIdx.x;
    const int to  = lid & 15;
    const int tp  = lid >> 4;

    {
        const int il  = lid & 31;
        const int seg = lid >> 5;
        float s = 0.0f;
        #pragma unroll
        for (int j = 0; j < 32; j++)
            s += x[(seg * 32 + j) * IN_ + i0 + il];
        ps[seg][il] = s;
    }

    float acc0 = 0.f, acc1 = 0.f;

    for (int bb = 0; bb < B_; bb += 128) {
        #pragma unroll
        for (int k = 0; k < 4; k++) {
            int e   = lid + k * 256;
            int row = e >> 3;
            int c4  = (e & 7) * 4;
            float4 xv = *(const float4*)&x[(bb + row) * IN_ + i0 + c4];
            float4 rv;
            rv.x = 1.0f / (xv.x + EPS_);
            rv.y = 1.0f / (xv.y + EPS_);
            rv.z = 1.0f / (xv.z + EPS_);
            rv.w = 1.0f / (xv.w + EPS_);
            *(float4*)&Rs[row][c4] = rv;
        }
        #pragma unroll
        for (int k = 0; k < 2; k++) {
            int e   = lid + k * 256;
            int row = e >> 2;
            int c4  = (e & 3) * 4;
            *(float4*)&Ts[row][c4] = *(const float4*)&t[(bb + row) * OUT_ + o0 + c4];
        }
        __syncthreads();

        if (bb == 0 && lid < 32) {
            float s = ps[0][lid];
            #pragma unroll
            for (int c = 1; c < 8; c++) s += ps[c][lid];
            s_cs[lid] = s;
        }

        #pragma unroll 8
        for (int b = 0; b < 128; b++) {
            float2 r  = *(const float2*)&Rs[b][2 * tp];
            float  tv = Ts[b][to];
            acc0 += fminf(tv * r.x, 1.0f);
            acc1 += fminf(tv * r.y, 1.0f);
        }
        __syncthreads();
    }

    const int i_0 = i0 + 2 * tp, i_1 = i_0 + 1;
    const int o   = o0 + to;
    g_relx[i_0 * OUT_ + o] = acc0 / s_cs[2 * tp];
    g_relx[i_1 * OUT_ + o] = acc1 / s_cs[2 * tp + 1];
}

// ---------------------------------------------------------------------------
// Kernel 2: cluster (1,1,2): two blocks split the i-range of one 32b x 32o
// tile. Each computes a partial argmax (select-tracking 2b x 2o, exact first
// max). z=1 publishes packed keys in smem; z=0 combines via DSMEM, gathers,
// writes outx/outw. Grid (8,16,2)=256 blocks, 256 thr.
// ---------------------------------------------------------------------------
__global__ void __cluster_dims__(1, 1, 2)
k_argmax(const float* __restrict__ x,
         const float* __restrict__ w,
         float* __restrict__ outx,
         float* __restrict__ outw) {
    __shared__ float Xs[128][34];              // [i][b_local] transposed, padded
    __shared__ float Rl[128][32];              // [i][o_local]
    __shared__ unsigned long long k_sh[1024];  // z=1 packed keys
    __shared__ float sv[8][32];
    __shared__ int   si[8][32];
    __shared__ float s_wv[32];
    __shared__ int   s_iw[32];

    const int b0  = blockIdx.x * 32;
    const int o0  = blockIdx.y * 32;
    const int z   = blockIdx.z;
    const int iz  = z * 128;
    const int lid = threadIdx.x;
    const int tb  = lid & 15;    // b pair: 2tb, 2tb+1
    const int to  = lid >> 4;    // o pair: 2to, 2to+1

    // --- w-argmax prologue (z==0 only): thread (ic, ol) scans 32 i's ---
    if (z == 0) {
        const int ol = lid & 31;
        const int ic = lid >> 5;
        const int o  = o0 + ol;
        float best = -1.f;
        int   bi   = 0;
        #pragma unroll
        for (int j = 0; j < 32; j++) {
            int i = ic * 32 + j;
            float v = w[i * OUT_ + o];
            if (v > best) { best = v; bi = i; }
        }
        sv[ic][ol] = best;
        si[ic][ol] = bi;
    }

    // --- stage this half's Xs (transposed) and Rl ---
    #pragma unroll
    for (int k = 0; k < 2; k++) {
        int e   = lid + k * 256;        // 0..511
        int row = e >> 5;               // 0..15 (b pair index)
        int c4  = (e & 31) * 4;         // i-local 0..124
        float4 v0 = *(const float4*)&x[(b0 + 2 * row)     * IN_ + iz + c4];
        float4 v1 = *(const float4*)&x[(b0 + 2 * row + 1) * IN_ + iz + c4];
        Xs[c4 + 0][2 * row] = v0.x;  Xs[c4 + 0][2 * row + 1] = v1.x;
        Xs[c4 + 1][2 * row] = v0.y;  Xs[c4 + 1][2 * row + 1] = v1.y;
        Xs[c4 + 2][2 * row] = v0.z;  Xs[c4 + 2][2 * row + 1] = v1.z;
        Xs[c4 + 3][2 * row] = v0.w;  Xs[c4 + 3][2 * row + 1] = v1.w;
    }
    #pragma unroll
    for (int k = 0; k < 4; k++) {
        int e   = lid + k * 256;
        int row = e >> 3;
        int c4  = (e & 7) * 4;
        *(float4*)&Rl[row][c4] = *(const float4*)&g_relx[(iz + row) * OUT_ + o0 + c4];
    }
    __syncthreads();

    if (z == 0 && lid < 32) {           // reduce w-argmax partials
        float bv = sv[0][lid];
        int   ix = si[0][lid];
        #pragma unroll
        for (int c = 1; c < 8; c++)
            if (sv[c][lid] > bv) { bv = sv[c][lid]; ix = si[c][lid]; }
        s_wv[lid] = bv;
        s_iw[lid] = ix;
    }

    // --- partial argmax over this half (select tracking, exact first-max) ---
    float best00 = -1.f, best01 = -1.f, best10 = -1.f, best11 = -1.f;
    int   id00 = iz, id01 = iz, id10 = iz, id11 = iz;

    #pragma unroll 4
    for (int i = 0; i < 128; i++) {
        const int gi = iz + i;
        float2 xv = *(const float2*)&Xs[i][2 * tb];
        float2 rv = *(const float2*)&Rl[i][2 * to];
        float v;
        v = xv.x * rv.x; { bool p = v > best00; best00 = fmaxf(best00, v); if (p) id00 = gi; }
        v = xv.x * rv.y; { bool p = v > best01; best01 = fmaxf(best01, v); if (p) id01 = gi; }
        v = xv.y * rv.x; { bool p = v > best10; best10 = fmaxf(best10, v); if (p) id10 = gi; }
        v = xv.y * rv.y; { bool p = v > best11; best11 = fmaxf(best11, v); if (p) id11 = gi; }
    }

    // --- z==1 publishes packed keys; z==0 combines via DSMEM and outputs ---
    if (z == 1) {
        k_sh[lid * 4 + 0] = ((unsigned long long)__float_as_uint(best00) << 32) | (unsigned)(~id00);
        k_sh[lid * 4 + 1] = ((unsigned long long)__float_as_uint(best01) << 32) | (unsigned)(~id01);
        k_sh[lid * 4 + 2] = ((unsigned long long)__float_as_uint(best10) << 32) | (unsigned)(~id10);
        k_sh[lid * 4 + 3] = ((unsigned long long)__float_as_uint(best11) << 32) | (unsigned)(~id11);
    }

    CLUSTER_SYNC();

    if (z == 0) {
        unsigned base = smem_u32(k_sh);
        unsigned peer;
        asm volatile("mapa.shared::cluster.u32 %0, %1, %2;"
                     : "=r"(peer) : "r"(base), "r"(1));

        unsigned long long pk[4];
        #pragma unroll
        for (int q = 0; q < 4; q++) {
            asm volatile("ld.shared::cluster.b64 %0, [%1];"
                         : "=l"(pk[q]) : "r"(peer + (unsigned)(lid * 4 + q) * 8));
        }

        unsigned long long k0, kk;
        int f00, f01, f10, f11;
        k0 = ((unsigned long long)__float_as_uint(best00) << 32) | (unsigned)(~id00);
        kk = (k0 >= pk[0]) ? k0 : pk[0];  f00 = (int)(~(unsigned)kk);
        k0 = ((unsigned long long)__float_as_uint(best01) << 32) | (unsigned)(~id01);
        kk = (k0 >= pk[1]) ? k0 : pk[1];  f01 = (int)(~(unsigned)kk);
        k0 = ((unsigned long long)__float_as_uint(best10) << 32) | (unsigned)(~id10);
        kk = (k0 >= pk[2]) ? k0 : pk[2];  f10 = (int)(~(unsigned)kk);
        k0 = ((unsigned long long)__float_as_uint(best11) << 32) | (unsigned)(~id11);
        kk = (k0 >= pk[3]) ? k0 : pk[3];  f11 = (int)(~(unsigned)kk);

        const int b_0 = b0 + 2 * tb, b_1 = b_0 + 1;
        const int o_0 = o0 + 2 * to;

        float2 ox0, ox1;
        ox0.x = x[b_0 * IN_ + f00] * w[f00 * OUT_ + o_0];
        ox0.y = x[b_0 * IN_ + f01] * w[f01 * OUT_ + o_0 + 1];
        ox1.x = x[b_1 * IN_ + f10] * w[f10 * OUT_ + o_0];
        ox1.y = x[b_1 * IN_ + f11] * w[f11 * OUT_ + o_0 + 1];
        *(float2*)&outx[b_0 * OUT_ + o_0] = ox0;
        *(float2*)&outx[b_1 * OUT_ + o_0] = ox1;

        const int lo0 = 2 * to, lo1 = 2 * to + 1;
        const int iw0 = s_iw[lo0], iw1 = s_iw[lo1];
        const float wv0 = s_wv[lo0], wv1 = s_wv[lo1];
        float2 ow0, ow1;
        ow0.x = x[b_0 * IN_ + iw0] * wv0;
        ow0.y = x[b_0 * IN_ + iw1] * wv1;
        ow1.x = x[b_1 * IN_ + iw0] * wv0;
        ow1.y = x[b_1 * IN_ + iw1] * wv1;
        *(float2*)&outw[b_0 * OUT_ + o_0] = ow0;
        *(float2*)&outw[b_1 * OUT_ + o_0] = ow1;
    }

    CLUSTER_SYNC();   // z=1 must stay alive while z=0 reads its smem
}

// ---------------------------------------------------------------------------
extern "C" void kernel_launch(void* const* d_in, const int* in_sizes, int n_in,
                              void* d_out, int out_size) {
    const float* x = (const float*)d_in[0];
    const float* w = (const float*)d_in[1];
    const float* t = (const float*)d_in[2];
    float* outx = (float*)d_out;
    float* outw = (float*)d_out + B_ * OUT_;

    k_relx  <<<dim3(IN_ / 32, OUT_ / 16), 256>>>(x, t);
    k_argmax<<<dim3(B_  / 32, OUT_ / 32, 2), 256>>>(x, w, outx, outw);
}